// round 9
// baseline (speedup 1.0000x reference)
#include <cuda_runtime.h>

// Fixed shapes: n=2, c=64, s=4, h=64, w=44
#define N_  2
#define C_  64
#define S_  4
#define H_  64
#define W_  44
#define B_  (N_ * S_)            // 8 effective batches
#define P_  (H_ * W_)            // 2816 pixels
#define R_  3
#define KT  49

#define TH  2                    // tile rows per block
#define CC  8                    // channels staged per chunk
#define NCH (C_ / CC)            // 8 chunks
#define G_  8                    // threads (tap-groups) per pixel
#define NTAP 7                   // max taps per group (g==0: 7, others: 6)
#define HALO_H (TH + 2 * R_)     // 8 shared rows
#define SW  52                   // 50 used cols + 2 pad (stride mod 32 = 20)
#define NTHREADS (W_ * TH * G_)  // 704

#define NF1 4                    // f1 elems staged per thread per chunk (8*8*44/704)
#define CHSTRIDE (S_ * P_)       // per-channel element stride

__global__ __launch_bounds__(NTHREADS, 2)
void corr_flow_kernel(const float* __restrict__ f0g,
                      const float* __restrict__ f1g,
                      float* __restrict__ out) {
    __shared__ float f1s[2][CC][HALO_H][SW];   // 2*8*8*52*4 = 26624 B
    __shared__ float f0s[2][CC][TH][W_];       // 2*8*2*44*4 =  5632 B

    const int tid = threadIdx.x;
    const int g   = tid & (G_ - 1);           // tap group 0..7
    const int p   = tid >> 3;                 // pixel in tile 0..87
    const int tx  = p % W_;
    const int ty  = p / W_;

    const int blk   = blockIdx.x;             // 0..255
    const int b     = blk >> 5;               // 0..7
    const int ytile = blk & 31;               // 0..31
    const int y0    = ytile * TH;
    const int n_idx = b / S_;
    const int s_idx = b - n_idx * S_;

    const int base = (n_idx * C_ * S_ + s_idx) * P_;

    // ---- precompute staging maps (chunk-invariant) ----
    int f1_s[NF1];
    int f1_g[NF1];
#pragma unroll
    for (int k = 0; k < NF1; k++) {
        int i   = tid + k * NTHREADS;
        int cc  = i / (HALO_H * W_);
        int rem = i - cc * (HALO_H * W_);
        int r   = rem / W_;
        int x   = rem - r * W_;
        int gy  = y0 - R_ + r;
        f1_s[k] = cc * (HALO_H * SW) + r * SW + x + R_;
        f1_g[k] = (gy >= 0 && gy < H_) ? (base + cc * CHSTRIDE + gy * W_ + x) : -1;
    }
    int f0_s0, f0_g0;
    {
        int i   = tid;
        int cc  = i / (TH * W_);
        int rem = i - cc * (TH * W_);
        int r   = rem / W_;
        int x   = rem - r * W_;
        f0_s0 = i;
        f0_g0 = base + cc * CHSTRIDE + (y0 + r) * W_ + x;
    }

    // per-thread tap offsets in a f1 plane: tap t = g + 8*i
    int off[NTAP];
#pragma unroll
    for (int i = 0; i < NTAP; i++) {
        int t = g + G_ * i;
        if (t > 48) t = 48;
        off[i] = (t / 7) * SW + (t % 7);
    }
    float acc[NTAP];
#pragma unroll
    for (int i = 0; i < NTAP; i++) acc[i] = 0.f;

    // zero both f1 buffers once (x-halo cols & out-of-image rows stay zero)
    {
        float* zp = &f1s[0][0][0][0];
        for (int i = tid; i < 2 * CC * HALO_H * SW; i += NTHREADS) zp[i] = 0.f;
    }
    // RACE FIX: zero-fill must be globally visible before any thread stages
    // chunk-0 data (zero-writer and data-writer of a word are different threads).
    __syncthreads();

    const int last = (g == 0) ? NTAP : (NTAP - 1);

    // ---- prologue: prefetch chunk 0, store into buffer 0 ----
    float r1[NF1], r0;
#pragma unroll
    for (int k = 0; k < NF1; k++) r1[k] = (f1_g[k] >= 0) ? f1g[f1_g[k]] : 0.f;
    r0 = f0g[f0_g0];

    float* f1b0 = &f1s[0][0][0][0];
    float* f1b1 = &f1s[1][0][0][0];
    float* f0b0 = &f0s[0][0][0][0];
    float* f0b1 = &f0s[1][0][0][0];

#pragma unroll
    for (int k = 0; k < NF1; k++) f1b0[f1_s[k]] = r1[k];
    f0b0[f0_s0] = r0;
    __syncthreads();

    // ---- pipelined mainloop ----
#pragma unroll 2
    for (int c = 0; c < NCH; c++) {
        if (c < NCH - 1) {
            int ch_off = (c + 1) * CC * CHSTRIDE;
#pragma unroll
            for (int k = 0; k < NF1; k++)
                r1[k] = (f1_g[k] >= 0) ? f1g[f1_g[k] + ch_off] : 0.f;
            r0 = f0g[f0_g0 + ch_off];
        }

        const float* f1p = ((c & 1) ? f1b1 : f1b0) + ty * SW + tx;
        const float* f0p = ((c & 1) ? f0b1 : f0b0) + ty * W_ + tx;
#pragma unroll
        for (int cc = 0; cc < CC; cc++) {
            float a = f0p[cc * (TH * W_)];       // broadcast over 8 group lanes
            const float* fp = f1p + cc * (HALO_H * SW);
#pragma unroll
            for (int i = 0; i < NTAP; i++) {
                if (i < last) acc[i] = fmaf(a, fp[off[i]], acc[i]);
            }
        }

        if (c < NCH - 1) {
            float* f1d = (c & 1) ? f1b0 : f1b1;
            float* f0d = (c & 1) ? f0b0 : f0b1;
#pragma unroll
            for (int k = 0; k < NF1; k++) f1d[f1_s[k]] = r1[k];
            f0d[f0_s0] = r0;
            __syncthreads();
        }
    }

    // ---- epilogue: masked softmax over taps, split across 8 lanes ----
    const int x = tx;
    const int y = y0 + ty;
    const float scale = 0.125f;   // 1/sqrt(64)

    float m = -1e30f;
#pragma unroll
    for (int i = 0; i < NTAP; i++) {
        int t = g + G_ * i;
        if (t < KT) {
            int dx = t % 7 - R_;
            int dy = t / 7 - R_;
            int gx = x + dx, gy = y + dy;
            if (gx >= 0 && gx < W_ && gy >= 0 && gy < H_)
                m = fmaxf(m, acc[i] * scale);
        }
    }
    m = fmaxf(m, __shfl_xor_sync(0xffffffffu, m, 1));
    m = fmaxf(m, __shfl_xor_sync(0xffffffffu, m, 2));
    m = fmaxf(m, __shfl_xor_sync(0xffffffffu, m, 4));

    float se = 0.f, sx = 0.f, sy = 0.f;
#pragma unroll
    for (int i = 0; i < NTAP; i++) {
        int t = g + G_ * i;
        if (t < KT) {
            int dx = t % 7 - R_;
            int dy = t / 7 - R_;
            int gx = x + dx, gy = y + dy;
            if (gx >= 0 && gx < W_ && gy >= 0 && gy < H_) {
                float e = __expf(acc[i] * scale - m);
                se += e;
                sx += e * (float)dx;
                sy += e * (float)dy;
            }
        }
    }
    se += __shfl_xor_sync(0xffffffffu, se, 1);
    se += __shfl_xor_sync(0xffffffffu, se, 2);
    se += __shfl_xor_sync(0xffffffffu, se, 4);
    sx += __shfl_xor_sync(0xffffffffu, sx, 1);
    sx += __shfl_xor_sync(0xffffffffu, sx, 2);
    sx += __shfl_xor_sync(0xffffffffu, sx, 4);
    sy += __shfl_xor_sync(0xffffffffu, sy, 1);
    sy += __shfl_xor_sync(0xffffffffu, sy, 2);
    sy += __shfl_xor_sync(0xffffffffu, sy, 4);

    if (g == 0) {
        float inv = 1.0f / se;
        int ob = ((n_idx * 2) * S_ + s_idx) * P_ + y * W_ + x;
        out[ob]           = sx * inv;   // flow x
        out[ob + S_ * P_] = sy * inv;   // flow y
    }
}

extern "C" void kernel_launch(void* const* d_in, const int* in_sizes, int n_in,
                              void* d_out, int out_size) {
    const float* f0 = (const float*)d_in[0];
    const float* f1 = (const float*)d_in[1];
    float* out = (float*)d_out;
    corr_flow_kernel<<<B_ * (H_ / TH), NTHREADS>>>(f0, f1, out);
}

// round 12
// speedup vs baseline: 1.4901x; 1.4901x over previous
#include <cuda_runtime.h>

// Fixed shapes: n=2, c=64, s=4, h=64, w=44
#define N_  2
#define C_  64
#define S_  4
#define H_  64
#define W_  44
#define B_  (N_ * S_)            // 8 effective batches
#define P_  (H_ * W_)            // 2816 pixels
#define R_  3
#define KT  49

#define TH  4                    // tile rows per block
#define CC  8                    // channels staged per chunk
#define NCH (C_ / CC)            // 8 chunks
#define G_  4                    // threads per pixel (row-owners)
#define HALO_H (TH + 2 * R_)     // 10 shared rows
#define SW  56                   // padded row stride (mod 32 = 24 -> conflict-free)
#define NTHREADS (W_ * TH * G_)  // 704

#define NF1 5                    // f1 elems staged per thread per chunk (8*10*44/704)
#define NF0 2                    // f0 elems staged per thread per chunk
#define CHSTRIDE (S_ * P_)       // per-channel element stride
#define F1PLANE (HALO_H * SW)    // 560 floats per channel plane
#define F0PLANE (TH * W_)        // 176 floats per channel plane

__global__ __launch_bounds__(NTHREADS, 1)
void corr_flow_kernel(const float* __restrict__ f0g,
                      const float* __restrict__ f1g,
                      float* __restrict__ out) {
    __shared__ float f1s[2][CC][HALO_H][SW];   // 2*8*10*56*4 = 35840 B
    __shared__ float f0s[2][CC][TH][W_];       // 2*8*4*44*4  = 11264 B

    const int tid = threadIdx.x;
    const int g   = tid & (G_ - 1);           // row-group 0..3
    const int p   = tid >> 2;                 // pixel in tile 0..175
    const int tx  = p % W_;
    const int ty  = p / W_;

    const int blk   = blockIdx.x;             // 0..127
    const int b     = blk >> 4;
    const int ytile = blk & 15;
    const int y0    = ytile * TH;
    const int n_idx = b / S_;
    const int s_idx = b - n_idx * S_;

    const int base = (n_idx * C_ * S_ + s_idx) * P_;

    // rows owned by this lane: row1 = g, row2 = g+4 (lane 3: duplicate row 3, discarded)
    const int row1 = g;
    const int row2 = (g < 3) ? (g + 4) : 3;
    const bool has2 = (g < 3);

    // ---- precompute staging maps (chunk-invariant) ----
    int f1_s[NF1];
    int f1_g[NF1];
#pragma unroll
    for (int k = 0; k < NF1; k++) {
        int i   = tid + k * NTHREADS;
        int cc  = i / (HALO_H * W_);
        int rem = i - cc * (HALO_H * W_);
        int r   = rem / W_;
        int x   = rem - r * W_;
        int gy  = y0 - R_ + r;
        f1_s[k] = cc * F1PLANE + r * SW + x + R_;
        f1_g[k] = (gy >= 0 && gy < H_) ? (base + cc * CHSTRIDE + gy * W_ + x) : -1;
    }
    int f0_s[NF0];
    int f0_g[NF0];
#pragma unroll
    for (int k = 0; k < NF0; k++) {
        int i   = tid + k * NTHREADS;
        int cc  = i / (TH * W_);
        int rem = i - cc * (TH * W_);
        int r   = rem / W_;
        int x   = rem - r * W_;
        f0_s[k] = i;
        f0_g[k] = base + cc * CHSTRIDE + (y0 + r) * W_ + x;
    }

    float acc1[7], acc2[7];
#pragma unroll
    for (int i = 0; i < 7; i++) { acc1[i] = 0.f; acc2[i] = 0.f; }

    // zero both f1 buffers once (x-halo cols & out-of-image rows stay zero)
    {
        float* zp = &f1s[0][0][0][0];
        for (int i = tid; i < 2 * CC * HALO_H * SW; i += NTHREADS) zp[i] = 0.f;
    }
    // zero-fill must be visible before chunk-0 staging (different writer threads)
    __syncthreads();

    // ---- prologue: prefetch chunk 0, store into buffer 0 ----
    float r1[NF1], r0[NF0];
#pragma unroll
    for (int k = 0; k < NF1; k++) r1[k] = (f1_g[k] >= 0) ? f1g[f1_g[k]] : 0.f;
#pragma unroll
    for (int k = 0; k < NF0; k++) r0[k] = f0g[f0_g[k]];

    float* f1b0 = &f1s[0][0][0][0];
    float* f1b1 = &f1s[1][0][0][0];
    float* f0b0 = &f0s[0][0][0][0];
    float* f0b1 = &f0s[1][0][0][0];

#pragma unroll
    for (int k = 0; k < NF1; k++) f1b0[f1_s[k]] = r1[k];
#pragma unroll
    for (int k = 0; k < NF0; k++) f0b0[f0_s[k]] = r0[k];
    __syncthreads();

    // ---- pipelined mainloop ----
#pragma unroll 2
    for (int c = 0; c < NCH; c++) {
        if (c < NCH - 1) {
            int ch_off = (c + 1) * CC * CHSTRIDE;
#pragma unroll
            for (int k = 0; k < NF1; k++)
                r1[k] = (f1_g[k] >= 0) ? f1g[f1_g[k] + ch_off] : 0.f;
#pragma unroll
            for (int k = 0; k < NF0; k++)
                r0[k] = f0g[f0_g[k] + ch_off];
        }

        // base pointers: all per-cc and per-tap offsets are compile-time imms
        const float* f1p = ((c & 1) ? f1b1 : f1b0) + ty * SW + tx;
        const float* r1p = f1p + row1 * SW;
        const float* r2p = f1p + row2 * SW;
        const float* f0p = ((c & 1) ? f0b1 : f0b0) + ty * W_ + tx;

#pragma unroll
        for (int cc = 0; cc < CC; cc++) {
            float a = f0p[cc * F0PLANE];            // broadcast over 4 lanes
#pragma unroll
            for (int i = 0; i < 7; i++) {
                acc1[i] = fmaf(a, r1p[cc * F1PLANE + i], acc1[i]);
                acc2[i] = fmaf(a, r2p[cc * F1PLANE + i], acc2[i]);
            }
        }

        if (c < NCH - 1) {
            float* f1d = (c & 1) ? f1b0 : f1b1;
            float* f0d = (c & 1) ? f0b0 : f0b1;
#pragma unroll
            for (int k = 0; k < NF1; k++) f1d[f1_s[k]] = r1[k];
#pragma unroll
            for (int k = 0; k < NF0; k++) f0d[f0_s[k]] = r0[k];
            __syncthreads();
        }
    }

    // ---- epilogue: masked softmax over owned taps, reduce across 4 lanes ----
    const int x = tx;
    const int y = y0 + ty;
    const float scale = 0.125f;   // 1/sqrt(64)
    const int dy1 = row1 - R_;
    const int dy2 = row2 - R_;
    const bool vy1 = (y + dy1 >= 0) && (y + dy1 < H_);
    const bool vy2 = has2 && (y + dy2 >= 0) && (y + dy2 < H_);

    float m = -1e30f;
#pragma unroll
    for (int i = 0; i < 7; i++) {
        int dx = i - R_;
        bool vx = (x + dx >= 0) && (x + dx < W_);
        if (vx && vy1) m = fmaxf(m, acc1[i] * scale);
        if (vx && vy2) m = fmaxf(m, acc2[i] * scale);
    }
    m = fmaxf(m, __shfl_xor_sync(0xffffffffu, m, 1));
    m = fmaxf(m, __shfl_xor_sync(0xffffffffu, m, 2));

    float se = 0.f, sx = 0.f, sy = 0.f;
#pragma unroll
    for (int i = 0; i < 7; i++) {
        int dx = i - R_;
        bool vx = (x + dx >= 0) && (x + dx < W_);
        if (vx && vy1) {
            float e = __expf(acc1[i] * scale - m);
            se += e; sx += e * (float)dx; sy += e * (float)dy1;
        }
        if (vx && vy2) {
            float e = __expf(acc2[i] * scale - m);
            se += e; sx += e * (float)dx; sy += e * (float)dy2;
        }
    }
    se += __shfl_xor_sync(0xffffffffu, se, 1);
    se += __shfl_xor_sync(0xffffffffu, se, 2);
    sx += __shfl_xor_sync(0xffffffffu, sx, 1);
    sx += __shfl_xor_sync(0xffffffffu, sx, 2);
    sy += __shfl_xor_sync(0xffffffffu, sy, 1);
    sy += __shfl_xor_sync(0xffffffffu, sy, 2);

    if (g == 0) {
        float inv = 1.0f / se;
        int ob = ((n_idx * 2) * S_ + s_idx) * P_ + y * W_ + x;
        out[ob]           = sx * inv;   // flow x
        out[ob + S_ * P_] = sy * inv;   // flow y
    }
}

extern "C" void kernel_launch(void* const* d_in, const int* in_sizes, int n_in,
                              void* d_out, int out_size) {
    const float* f0 = (const float*)d_in[0];
    const float* f1 = (const float*)d_in[1];
    float* out = (float*)d_out;
    corr_flow_kernel<<<B_ * (H_ / TH), NTHREADS>>>(f0, f1, out);
}